// round 12
// baseline (speedup 1.0000x reference)
#include <cuda_runtime.h>
#include <cuda_bf16.h>
#include <cstdint>

// ---------------- problem constants ----------------
#define N_USERS   50000
#define N_ITEMS   10000
#define N_NODES   100000
#define EMB       64
#define NNZ       1600000
#define VIS_DIM   2048
#define TXT_DIM   300
#define OUT_COLS  192   // emb * 3

// ---------------- device scratch (static, allocation-free) ----------------
__device__ float g_H1v[N_ITEMS * 512];    // relu(visual @ Wv1^T + bv1)
__device__ float g_H1t[N_ITEMS * 256];    // relu(text  @ Wt1^T + bt1)
__device__ float g_nb [N_NODES * EMB];    // SpMM accumulator
__device__ float g_Wv2d[64 * 512];        // Wd @ Wv2
__device__ float g_Wt2d[64 * 256];        // Wd @ Wt2
__device__ float g_bfuse[64];             // Wd@(bv2+bt2) + 2*bd
// tf32-pre-rounded copies of the big MLP inputs (bit-identical to in-loop cvt)
__device__ float g_vis_t[N_ITEMS * VIS_DIM];   // 82 MB
__device__ float g_txt_t[N_ITEMS * TXT_DIM];   // 12 MB
__device__ float g_Wv1_t[512 * VIS_DIM];       // 4.2 MB
__device__ float g_Wt1_t[256 * TXT_DIM];       // 0.3 MB

// ---------------- fp32 -> tf32(rna) elementwise pre-pass ----------------
__global__ void cvt_tf32(const float4* __restrict__ in, float4* __restrict__ out, int n4)
{
    int i = blockIdx.x * blockDim.x + threadIdx.x;
    if (i >= n4) return;
    float4 v = in[i];
    uint32_t x0 = __float_as_uint(v.x), x1 = __float_as_uint(v.y);
    uint32_t x2 = __float_as_uint(v.z), x3 = __float_as_uint(v.w);
    asm("cvt.rna.tf32.f32 %0, %0;" : "+r"(x0));
    asm("cvt.rna.tf32.f32 %0, %0;" : "+r"(x1));
    asm("cvt.rna.tf32.f32 %0, %0;" : "+r"(x2));
    asm("cvt.rna.tf32.f32 %0, %0;" : "+r"(x3));
    out[i] = make_float4(__uint_as_float(x0), __uint_as_float(x1),
                         __uint_as_float(x2), __uint_as_float(x3));
}

// ---------------- weight combination (tiny) ----------------
__global__ void combine_w(const float* __restrict__ Wd, const float* __restrict__ bd,
                          const float* __restrict__ Wv2, const float* __restrict__ bv2,
                          const float* __restrict__ Wt2, const float* __restrict__ bt2)
{
    int idx = blockIdx.x * blockDim.x + threadIdx.x;
    if (idx < 64 * 512) {
        int d = idx >> 9, k = idx & 511;
        float s = 0.f;
        #pragma unroll 8
        for (int o = 0; o < 64; o++) s += Wd[d * 64 + o] * Wv2[o * 512 + k];
        g_Wv2d[idx] = s;
    } else if (idx < 64 * 512 + 64 * 256) {
        int j = idx - 64 * 512;
        int d = j >> 8, k = j & 255;
        float s = 0.f;
        #pragma unroll 8
        for (int o = 0; o < 64; o++) s += Wd[d * 64 + o] * Wt2[o * 256 + k];
        g_Wt2d[j] = s;
    } else if (idx < 64 * 512 + 64 * 256 + 64) {
        int d = idx - (64 * 512 + 64 * 256);
        float s = 2.f * bd[d];
        #pragma unroll 8
        for (int o = 0; o < 64; o++) s += Wd[d * 64 + o] * (bv2[o] + bt2[o]);
        g_bfuse[d] = s;
    }
}

// ---------------- ego copy: embedding -> out[:, 0:64] ----------------
__global__ void copy_ego(const float* __restrict__ emb, float* __restrict__ out)
{
    int i = blockIdx.x * blockDim.x + threadIdx.x;   // over N_NODES*16 float4s
    if (i >= N_NODES * 16) return;
    int row = i >> 4, c = i & 15;
    *(float4*)(out + (size_t)row * OUT_COLS + c * 4) =
        *(const float4*)(emb + (size_t)row * EMB + c * 4);
}

// ---------------- zero SpMM accumulator ----------------
__global__ void zero_nb()
{
    int i = blockIdx.x * blockDim.x + threadIdx.x;
    if (i < N_NODES * 16) ((float4*)g_nb)[i] = make_float4(0.f, 0.f, 0.f, 0.f);
}

// ---------------- tf32 tensor-core GEMM: C = relu(A @ B^T + bias) --------
// A [M,K] row-major, B [N,K] row-major, BOTH ALREADY tf32-ROUNDED.
// BM=BN=128, BK=16, 256 threads, 8 warps x (64x32) mma.m16n8k8.tf32.
// cp.async double buffer. N must be a multiple of 128. Non-VEC4 zero-fills K tail.
template <bool VEC4>
__global__ __launch_bounds__(256, 2)
void mma_nt_relu(const float* __restrict__ A, const float* __restrict__ B,
                 const float* __restrict__ bias, float* __restrict__ C,
                 int M, int N, int K)
{
    const int BK = 16, LDT = 20;   // +4 pad: ldmatrix rows land on disjoint bank quads
    __shared__ float As[2][128][LDT];
    __shared__ float Bs[2][128][LDT];

    int tid = threadIdx.x;
    int lane = tid & 31, wid = tid >> 5;
    int wm = wid >> 2;     // 0..1 : 64-row half
    int wn = wid & 3;      // 0..3 : 32-col quarter

    int row  = tid >> 1;          // 0..127
    int koff = (tid & 1) * 8;     // 0 or 8
    int aRow = blockIdx.y * 128 + row;
    int aRowC = aRow < M ? aRow : M - 1;
    int bRow = blockIdx.x * 128 + row;    // always < N (N % 128 == 0)
    const float* Arow = A + (size_t)aRowC * K + koff;
    const float* Brow = B + (size_t)bRow  * K + koff;

    uint32_t uA[2], uB[2];
    uA[0] = (uint32_t)__cvta_generic_to_shared(&As[0][row][koff]);
    uA[1] = (uint32_t)__cvta_generic_to_shared(&As[1][row][koff]);
    uB[0] = (uint32_t)__cvta_generic_to_shared(&Bs[0][row][koff]);
    uB[1] = (uint32_t)__cvta_generic_to_shared(&Bs[1][row][koff]);

    auto issue = [&](int k0, int buf) {
        #pragma unroll
        for (int c = 0; c < 2; c++) {
            int sz;
            if (VEC4) sz = 16;
            else {
                int rem = K - (k0 + koff + c * 4);      // floats still valid
                sz = rem >= 4 ? 16 : (rem > 0 ? rem * 4 : 0);
            }
            asm volatile("cp.async.ca.shared.global [%0], [%1], 16, %2;"
                         :: "r"(uA[buf] + c * 16), "l"(Arow + k0 + c * 4), "r"(sz) : "memory");
            asm volatile("cp.async.ca.shared.global [%0], [%1], 16, %2;"
                         :: "r"(uB[buf] + c * 16), "l"(Brow + k0 + c * 4), "r"(sz) : "memory");
        }
        asm volatile("cp.async.commit_group;" ::: "memory");
    };

    int l = lane & 7;
    int selA = lane >> 3;
    int arow0 = wm * 64 + (selA & 1) * 8 + l;
    int acol0 = (selA >> 1) * 4;
    uint32_t aBase[2];
    aBase[0] = (uint32_t)__cvta_generic_to_shared(&As[0][arow0][acol0]);
    aBase[1] = (uint32_t)__cvta_generic_to_shared(&As[1][arow0][acol0]);
    int l16 = lane & 15;
    int brow0 = wn * 32 + (l16 & 7);
    int bcol0 = (l16 >> 3) * 4;
    uint32_t bBase[2];
    bBase[0] = (uint32_t)__cvta_generic_to_shared(&Bs[0][brow0][bcol0]);
    bBase[1] = (uint32_t)__cvta_generic_to_shared(&Bs[1][brow0][bcol0]);

    float acc[4][4][4];
    #pragma unroll
    for (int i = 0; i < 4; i++)
        #pragma unroll
        for (int j = 0; j < 4; j++)
            #pragma unroll
            for (int r = 0; r < 4; r++) acc[i][j][r] = 0.f;

    int T = (K + BK - 1) / BK;
    issue(0, 0);
    asm volatile("cp.async.wait_group 0;" ::: "memory");
    __syncthreads();

    for (int t = 0; t < T; t++) {
        if (t + 1 < T) issue((t + 1) * BK, (t + 1) & 1);

        int cur = t & 1;
        #pragma unroll
        for (int ks = 0; ks < 2; ks++) {
            uint32_t af[4][4], bf[4][2];
            #pragma unroll
            for (int i = 0; i < 4; i++) {
                uint32_t addr = aBase[cur] + (uint32_t)((i * 16 * LDT + ks * 8) * 4);
                asm volatile("ldmatrix.sync.aligned.m8n8.x4.shared.b16 {%0,%1,%2,%3}, [%4];"
                    : "=r"(af[i][0]), "=r"(af[i][1]), "=r"(af[i][2]), "=r"(af[i][3])
                    : "r"(addr));
            }
            #pragma unroll
            for (int j = 0; j < 4; j++) {
                uint32_t addr = bBase[cur] + (uint32_t)((j * 8 * LDT + ks * 8) * 4);
                asm volatile("ldmatrix.sync.aligned.m8n8.x2.shared.b16 {%0,%1}, [%2];"
                    : "=r"(bf[j][0]), "=r"(bf[j][1])
                    : "r"(addr));
            }
            // inputs are pre-rounded tf32 -> no cvt in the mainloop
            #pragma unroll
            for (int i = 0; i < 4; i++)
                #pragma unroll
                for (int j = 0; j < 4; j++)
                    asm volatile(
                        "mma.sync.aligned.m16n8k8.row.col.f32.tf32.tf32.f32 "
                        "{%0,%1,%2,%3}, {%4,%5,%6,%7}, {%8,%9}, {%0,%1,%2,%3};"
                        : "+f"(acc[i][j][0]), "+f"(acc[i][j][1]),
                          "+f"(acc[i][j][2]), "+f"(acc[i][j][3])
                        : "r"(af[i][0]), "r"(af[i][1]), "r"(af[i][2]), "r"(af[i][3]),
                          "r"(bf[j][0]), "r"(bf[j][1]));
        }

        if (t + 1 < T) asm volatile("cp.async.wait_group 0;" ::: "memory");
        __syncthreads();
    }

    int g = lane >> 2, tq = lane & 3;
    #pragma unroll
    for (int i = 0; i < 4; i++) {
        int m0 = blockIdx.y * 128 + wm * 64 + i * 16 + g;
        #pragma unroll
        for (int j = 0; j < 4; j++) {
            int n0 = blockIdx.x * 128 + wn * 32 + j * 8 + 2 * tq;
            float bv0 = bias[n0], bv1 = bias[n0 + 1];
            if (m0 < M) {
                float2 v = make_float2(fmaxf(acc[i][j][0] + bv0, 0.f),
                                       fmaxf(acc[i][j][1] + bv1, 0.f));
                *(float2*)(C + (size_t)m0 * N + n0) = v;
            }
            if (m0 + 8 < M) {
                float2 v = make_float2(fmaxf(acc[i][j][2] + bv0, 0.f),
                                       fmaxf(acc[i][j][3] + bv1, 0.f));
                *(float2*)(C + (size_t)(m0 + 8) * N + n0) = v;
            }
        }
    }
}

// ---------------- tf32 small GEMM, N=64, split-K two-part inputs ---------
// C[m,n] = epi( A1@B1^T + A2@B2^T + bias ), mode 0: *0.5, mode 1: leaky_relu.
// BM=128, BN=64, BK=16, 8 warps x (32x32) via mma.m16n8k8.tf32 (in-loop cvt).
// Requires K1 % 16 == 0, K2 % 16 == 0, 16B-aligned rows.
__global__ __launch_bounds__(256, 3)
void gemm_n64(const float* __restrict__ A1, int lda1, int K1,
              const float* __restrict__ A2, int lda2, int K2,
              const float* __restrict__ B1, int ldb1,
              const float* __restrict__ B2, int ldb2,
              const float* __restrict__ bias,
              float* __restrict__ C, int ldc, int M, int mode)
{
    const int BK = 16, LDT = 20;
    __shared__ float As[2][128][LDT];
    __shared__ float Bs[2][64][LDT];

    int tid = threadIdx.x;
    int lane = tid & 31, wid = tid >> 5;
    int wm = wid >> 1;     // 0..3 : 32-row quarter
    int wn = wid & 1;      // 0..1 : 32-col half

    int arow  = tid >> 1;
    int akoff = (tid & 1) * 8;
    int rA = blockIdx.x * 128 + arow;
    int rAc = rA < M ? rA : M - 1;
    int brow  = tid >> 2;
    int bkoff = (tid & 3) * 4;

    uint32_t uA[2], uB[2];
    uA[0] = (uint32_t)__cvta_generic_to_shared(&As[0][arow][akoff]);
    uA[1] = (uint32_t)__cvta_generic_to_shared(&As[1][arow][akoff]);
    uB[0] = (uint32_t)__cvta_generic_to_shared(&Bs[0][brow][bkoff]);
    uB[1] = (uint32_t)__cvta_generic_to_shared(&Bs[1][brow][bkoff]);

    auto issue = [&](int k0, int buf) {   // tiles never straddle the K1 boundary
        const float* Ap; const float* Bp; int lda, ldb, kb;
        if (k0 < K1) { Ap = A1; Bp = B1; lda = lda1; ldb = ldb1; kb = k0; }
        else         { Ap = A2; Bp = B2; lda = lda2; ldb = ldb2; kb = k0 - K1; }
        const float* as = Ap + (size_t)rAc * lda + kb + akoff;
        asm volatile("cp.async.ca.shared.global [%0], [%1], 16;"
                     :: "r"(uA[buf]), "l"(as) : "memory");
        asm volatile("cp.async.ca.shared.global [%0], [%1], 16;"
                     :: "r"(uA[buf] + 16), "l"(as + 4) : "memory");
        const float* bsrc = Bp + (size_t)brow * ldb + kb + bkoff;
        asm volatile("cp.async.ca.shared.global [%0], [%1], 16;"
                     :: "r"(uB[buf]), "l"(bsrc) : "memory");
        asm volatile("cp.async.commit_group;" ::: "memory");
    };

    int l = lane & 7;
    int selA = lane >> 3;
    int arow0 = wm * 32 + (selA & 1) * 8 + l;
    int acol0 = (selA >> 1) * 4;
    uint32_t aBase[2];
    aBase[0] = (uint32_t)__cvta_generic_to_shared(&As[0][arow0][acol0]);
    aBase[1] = (uint32_t)__cvta_generic_to_shared(&As[1][arow0][acol0]);
    int l16 = lane & 15;
    int brow0 = wn * 32 + (l16 & 7);
    int bcol0 = (l16 >> 3) * 4;
    uint32_t bBase[2];
    bBase[0] = (uint32_t)__cvta_generic_to_shared(&Bs[0][brow0][bcol0]);
    bBase[1] = (uint32_t)__cvta_generic_to_shared(&Bs[1][brow0][bcol0]);

    float acc[2][4][4];
    #pragma unroll
    for (int i = 0; i < 2; i++)
        #pragma unroll
        for (int j = 0; j < 4; j++)
            #pragma unroll
            for (int r = 0; r < 4; r++) acc[i][j][r] = 0.f;

    int T = (K1 + K2) / BK;
    issue(0, 0);
    asm volatile("cp.async.wait_group 0;" ::: "memory");
    __syncthreads();

    for (int t = 0; t < T; t++) {
        if (t + 1 < T) issue((t + 1) * BK, (t + 1) & 1);

        int cur = t & 1;
        #pragma unroll
        for (int ks = 0; ks < 2; ks++) {
            uint32_t af[2][4], bf[4][2];
            #pragma unroll
            for (int i = 0; i < 2; i++) {
                uint32_t addr = aBase[cur] + (uint32_t)((i * 16 * LDT + ks * 8) * 4);
                asm volatile("ldmatrix.sync.aligned.m8n8.x4.shared.b16 {%0,%1,%2,%3}, [%4];"
                    : "=r"(af[i][0]), "=r"(af[i][1]), "=r"(af[i][2]), "=r"(af[i][3])
                    : "r"(addr));
            }
            #pragma unroll
            for (int j = 0; j < 4; j++) {
                uint32_t addr = bBase[cur] + (uint32_t)((j * 8 * LDT + ks * 8) * 4);
                asm volatile("ldmatrix.sync.aligned.m8n8.x2.shared.b16 {%0,%1}, [%2];"
                    : "=r"(bf[j][0]), "=r"(bf[j][1])
                    : "r"(addr));
            }
            #pragma unroll
            for (int i = 0; i < 2; i++)
                #pragma unroll
                for (int r = 0; r < 4; r++)
                    asm("cvt.rna.tf32.f32 %0, %0;" : "+r"(af[i][r]));
            #pragma unroll
            for (int j = 0; j < 4; j++)
                #pragma unroll
                for (int r = 0; r < 2; r++)
                    asm("cvt.rna.tf32.f32 %0, %0;" : "+r"(bf[j][r]));

            #pragma unroll
            for (int i = 0; i < 2; i++)
                #pragma unroll
                for (int j = 0; j < 4; j++)
                    asm volatile(
                        "mma.sync.aligned.m16n8k8.row.col.f32.tf32.tf32.f32 "
                        "{%0,%1,%2,%3}, {%4,%5,%6,%7}, {%8,%9}, {%0,%1,%2,%3};"
                        : "+f"(acc[i][j][0]), "+f"(acc[i][j][1]),
                          "+f"(acc[i][j][2]), "+f"(acc[i][j][3])
                        : "r"(af[i][0]), "r"(af[i][1]), "r"(af[i][2]), "r"(af[i][3]),
                          "r"(bf[j][0]), "r"(bf[j][1]));
        }

        if (t + 1 < T) asm volatile("cp.async.wait_group 0;" ::: "memory");
        __syncthreads();
    }

    int g = lane >> 2, tq = lane & 3;
    #pragma unroll
    for (int i = 0; i < 2; i++) {
        int m0 = blockIdx.x * 128 + wm * 32 + i * 16 + g;
        #pragma unroll
        for (int j = 0; j < 4; j++) {
            int n0 = wn * 32 + j * 8 + 2 * tq;
            float bv0 = bias[n0], bv1 = bias[n0 + 1];
            #pragma unroll
            for (int h = 0; h < 2; h++) {
                int m = m0 + 8 * h;
                if (m < M) {
                    float t0 = acc[i][j][2 * h]     + bv0;
                    float t1 = acc[i][j][2 * h + 1] + bv1;
                    float2 v;
                    if (mode == 0) { v.x = 0.5f * t0; v.y = 0.5f * t1; }
                    else { v.x = t0 > 0.f ? t0 : 0.01f * t0;
                           v.y = t1 > 0.f ? t1 : 0.01f * t1; }
                    *(float2*)(C + (size_t)m * ldc + n0) = v;
                }
            }
        }
    }
}

// ---------------- SpMM scatter: nb[row] += val * cur[col] ----------------
__global__ __launch_bounds__(256)
void spmm_scatter(const int* __restrict__ rows, const int* __restrict__ cols,
                  const float* __restrict__ vals,
                  const float* __restrict__ cur, int ld_cur)
{
    long t = (long)blockIdx.x * blockDim.x + threadIdx.x;
    int e = (int)(t >> 4);
    int c = (int)(t & 15);
    if (e >= NNZ) return;
    int r = rows[e];
    int cl = cols[e];
    float v = vals[e];
    float4 x = *(const float4*)(cur + (size_t)cl * ld_cur + c * 4);
    float* dst = g_nb + (size_t)r * EMB + c * 4;
    asm volatile("red.global.add.v4.f32 [%0], {%1, %2, %3, %4};"
                 :: "l"(dst), "f"(x.x * v), "f"(x.y * v), "f"(x.z * v), "f"(x.w * v)
                 : "memory");
}

// ---------------- launch ----------------
extern "C" void kernel_launch(void* const* d_in, const int* in_sizes, int n_in,
                              void* d_out, int out_size)
{
    const int*   adj_row = (const int*)  d_in[0];
    const int*   adj_col = (const int*)  d_in[1];
    const float* adj_val = (const float*)d_in[2];
    const float* embedding = (const float*)d_in[3];
    const float* visual  = (const float*)d_in[4];
    const float* text    = (const float*)d_in[5];
    const float* Wv1 = (const float*)d_in[6];  const float* bv1 = (const float*)d_in[7];
    const float* Wv2 = (const float*)d_in[8];  const float* bv2 = (const float*)d_in[9];
    const float* Wt1 = (const float*)d_in[10]; const float* bt1 = (const float*)d_in[11];
    const float* Wt2 = (const float*)d_in[12]; const float* bt2 = (const float*)d_in[13];
    const float* Wd  = (const float*)d_in[14]; const float* bd  = (const float*)d_in[15];
    const float* Wc0 = (const float*)d_in[16]; const float* bc0 = (const float*)d_in[17];
    const float* Wc1 = (const float*)d_in[18]; const float* bc1 = (const float*)d_in[19];
    float* out = (float*)d_out;

    float *pH1v, *pH1t, *pNb, *pWv2d, *pWt2d, *pBfuse;
    float *pVisT, *pTxtT, *pWv1T, *pWt1T;
    cudaGetSymbolAddress((void**)&pH1v,  g_H1v);
    cudaGetSymbolAddress((void**)&pH1t,  g_H1t);
    cudaGetSymbolAddress((void**)&pNb,   g_nb);
    cudaGetSymbolAddress((void**)&pWv2d, g_Wv2d);
    cudaGetSymbolAddress((void**)&pWt2d, g_Wt2d);
    cudaGetSymbolAddress((void**)&pBfuse,g_bfuse);
    cudaGetSymbolAddress((void**)&pVisT, g_vis_t);
    cudaGetSymbolAddress((void**)&pTxtT, g_txt_t);
    cudaGetSymbolAddress((void**)&pWv1T, g_Wv1_t);
    cudaGetSymbolAddress((void**)&pWt1T, g_Wt1_t);

    // 0. pre-round MLP inputs to tf32 (rna) — removes cvt from MMA mainloops
    {
        int n4;
        n4 = N_ITEMS * VIS_DIM / 4;
        cvt_tf32<<<(n4 + 255) / 256, 256>>>((const float4*)visual, (float4*)pVisT, n4);
        n4 = N_ITEMS * TXT_DIM / 4;
        cvt_tf32<<<(n4 + 255) / 256, 256>>>((const float4*)text, (float4*)pTxtT, n4);
        n4 = 512 * VIS_DIM / 4;
        cvt_tf32<<<(n4 + 255) / 256, 256>>>((const float4*)Wv1, (float4*)pWv1T, n4);
        n4 = 256 * TXT_DIM / 4;
        cvt_tf32<<<(n4 + 255) / 256, 256>>>((const float4*)Wt1, (float4*)pWt1T, n4);
    }

    // 1. fold Wd into the second-layer weights/biases
    combine_w<<<(64*512 + 64*256 + 64 + 255) / 256, 256>>>(Wd, bd, Wv2, bv2, Wt2, bt2);

    // 2. ego = embedding (item rows overwritten by fusion below)
    copy_ego<<<(N_NODES * 16 + 255) / 256, 256>>>(embedding, out);

    // 3. H1v = relu(visual @ Wv1^T + bv1)   [10000, 512], K=2048  (tf32 MMA)
    {
        dim3 grid(512 / 128, (N_ITEMS + 127) / 128);
        mma_nt_relu<true><<<grid, 256>>>(pVisT, pWv1T, bv1, pH1v, N_ITEMS, 512, VIS_DIM);
    }
    // 4. H1t = relu(text @ Wt1^T + bt1)     [10000, 256], K=300   (tf32 MMA, tail-guarded)
    {
        dim3 grid(256 / 128, (N_ITEMS + 127) / 128);
        mma_nt_relu<false><<<grid, 256>>>(pTxtT, pWt1T, bt1, pH1t, N_ITEMS, 256, TXT_DIM);
    }
    // 5. fused_item -> ego item rows: 0.5*(H1v@Wv2d^T + H1t@Wt2d^T + bfuse)
    gemm_n64<<<(N_ITEMS + 127) / 128, 256>>>(
        pH1v, 512, 512, pH1t, 256, 256,
        pWv2d, 512, pWt2d, 256,
        pBfuse, out + (size_t)N_USERS * OUT_COLS, OUT_COLS, N_ITEMS, 0);

    // ---- layer 1 ----
    zero_nb<<<(N_NODES * 16 + 255) / 256, 256>>>();
    spmm_scatter<<<(int)(((long)NNZ * 16 + 255) / 256), 256>>>(
        adj_row, adj_col, adj_val, out /*ego, cols 0:64*/, OUT_COLS);
    gemm_n64<<<(N_NODES + 127) / 128, 256>>>(
        out, OUT_COLS, 64, pNb, EMB, 64,
        Wc0, 128, Wc0 + 64, 128,
        bc0, out + 64, OUT_COLS, N_NODES, 1);

    // ---- layer 2 ----
    zero_nb<<<(N_NODES * 16 + 255) / 256, 256>>>();
    spmm_scatter<<<(int)(((long)NNZ * 16 + 255) / 256), 256>>>(
        adj_row, adj_col, adj_val, out + 64 /*cur1, cols 64:128*/, OUT_COLS);
    gemm_n64<<<(N_NODES + 127) / 128, 256>>>(
        out + 64, OUT_COLS, 64, pNb, EMB, 64,
        Wc1, 128, Wc1 + 64, 128,
        bc1, out + 128, OUT_COLS, N_NODES, 1);
}